// round 3
// baseline (speedup 1.0000x reference)
#include <cuda_runtime.h>
#include <cstdint>

#define RR 5
#define NN 4096
#define DD 256
#define HH 64
#define BB 4096

// ---------------- scratch (static device globals; no allocs allowed) -------
__device__ float g_uw[RR*DD*HH];            // cumsum(u_weight)
__device__ float g_vw[RR*DD*HH];            // cumsum(v_weight)
__device__ float g_rowPart[RR*32*NN];       // partial row sums  [r][mchunk][n]
__device__ float g_colPart[RR*8*NN];        // partial col sums  [r][nchunk][m]
__device__ float g_cinv[RR*NN];             // rsqrt(row-sums)  (index n)
__device__ float g_rinv[RR*NN];             // rsqrt(col-sums)  (index m)
__device__ float g_Xh[(size_t)RR*HH*NN];    // X^T = (c_inv * tmp_u)^T  [r][h][n]
__device__ float g_Y [(size_t)RR*NN*HH];    // Y   = (r_inv * tmp_v)    [r][m][h]
__device__ float g_Tu[(size_t)RR*NN*HH];    // T_u  [r][n][h]
__device__ float g_Tvt[(size_t)RR*HH*NN];   // T_v^T [r][h][m]

// ---------------- pass 1: row/col sums of support (deterministic) ---------
__global__ void k_sums(const float* __restrict__ supp){
  const int r = blockIdx.z, mc = blockIdx.x, nc = blockIdx.y;
  const int m0 = mc*128, n0 = nc*512;
  const int w = threadIdx.x>>5, lane = threadIdx.x&31;
  const float* base = supp + (size_t)r*NN*NN + m0 + lane*4;
  float cx=0.f, cy=0.f, cz=0.f, cw=0.f;
  float* rp = g_rowPart + ((size_t)r*32 + mc)*NN;
  #pragma unroll 4
  for(int i=0;i<128;i++){
    const int n = n0 + w*128 + i;
    const float4 v = *reinterpret_cast<const float4*>(base + (size_t)n*NN);
    float s = v.x+v.y+v.z+v.w;
    cx+=v.x; cy+=v.y; cz+=v.z; cw+=v.w;
    #pragma unroll
    for(int o=16;o;o>>=1) s += __shfl_xor_sync(0xffffffffu, s, o);
    if(lane==0) rp[n] = s;
  }
  __shared__ float sc[4][128];
  sc[w][lane*4+0]=cx; sc[w][lane*4+1]=cy; sc[w][lane*4+2]=cz; sc[w][lane*4+3]=cw;
  __syncthreads();
  if(threadIdx.x < 128){
    float s = sc[0][threadIdx.x]+sc[1][threadIdx.x]+sc[2][threadIdx.x]+sc[3][threadIdx.x];
    g_colPart[((size_t)r*8 + nc)*NN + m0 + threadIdx.x] = s;
  }
}

// ---------------- pass 2: reduce partials -> c_inv / r_inv -----------------
__global__ void k_reduce(){
  const int idx = blockIdx.x*256 + threadIdx.x;   // grid 160 -> 40960 threads
  if(idx < RR*NN){
    const int r = idx/NN, n = idx%NN;
    float s=0.f;
    #pragma unroll
    for(int mc=0; mc<32; mc++) s += g_rowPart[((size_t)r*32+mc)*NN + n];
    g_cinv[idx] = (s>0.f)? rsqrtf(s) : 0.f;
  } else {
    const int j = idx - RR*NN;
    const int r = j/NN, m = j%NN;
    float s=0.f;
    #pragma unroll
    for(int nc=0; nc<8; nc++) s += g_colPart[((size_t)r*8+nc)*NN + m];
    g_rinv[j] = (s>0.f)? rsqrtf(s) : 0.f;
  }
}

// ---------------- weight cumsum over relations -----------------------------
__global__ void k_weights(const float* __restrict__ uw, const float* __restrict__ vw){
  const int i = blockIdx.x*256 + threadIdx.x;     // grid 64 -> 16384
  float au=0.f, av=0.f;
  #pragma unroll
  for(int r=0;r<RR;r++){
    au += uw[r*DD*HH + i]; g_uw[r*DD*HH + i] = au;
    av += vw[r*DD*HH + i]; g_vw[r*DD*HH + i] = av;
  }
}

// ---------------- small GEMMs: X^T and Y (scaled) --------------------------
__global__ void k_tmp(const float* __restrict__ u_feat, const float* __restrict__ v_feat){
  // grid (1024, RR, 2), block 256 = 4 rows x 64 h
  const int side = blockIdx.z, r = blockIdx.y;
  const int nb = blockIdx.x*4;
  const int rl = threadIdx.x>>6, h = threadIdx.x&63;
  const float* feat = side ? v_feat : u_feat;
  const float* wgt  = (side ? g_vw : g_uw) + r*DD*HH;
  __shared__ float sf[4][DD];
  for(int f = threadIdx.x; f < 4*DD; f += 256)
    sf[f>>8][f&255] = feat[(size_t)(nb + (f>>8))*DD + (f&255)];
  __syncthreads();
  float acc=0.f;
  #pragma unroll 8
  for(int d=0; d<DD; d++) acc += sf[rl][d]*wgt[d*HH + h];
  const int n = nb + rl;
  if(side==0){
    g_Xh[((size_t)r*HH + h)*NN + n] = acc * g_cinv[r*NN + n];
  } else {
    g_Y[((size_t)r*NN + n)*HH + h]  = acc * g_rinv[r*NN + n];
  }
}

// ---------------- TF32 helpers ---------------------------------------------
__device__ __forceinline__ unsigned f2tf(float x){
  unsigned r; asm("cvt.rna.tf32.f32 %0, %1;" : "=r"(r) : "f"(x)); return r;
}
__device__ __forceinline__ void mma8(float* c, const unsigned* a, const unsigned* b){
  asm volatile("mma.sync.aligned.m16n8k8.row.col.f32.tf32.tf32.f32 "
    "{%0,%1,%2,%3},{%4,%5,%6,%7},{%8,%9},{%0,%1,%2,%3};"
    : "+f"(c[0]),"+f"(c[1]),"+f"(c[2]),"+f"(c[3])
    : "r"(a[0]),"r"(a[1]),"r"(a[2]),"r"(a[3]),"r"(b[0]),"r"(b[1]));
}

#define SA_STR  36   // pad: conflict-free m16n8k8 A-frag reads
#define SBU_STR 68   // pad: conflict-free B-frag reads (64-wide)
#define SBV_STR 132  // pad: conflict-free B-frag reads (128-wide)

struct SmemU { unsigned a[128][SA_STR]; unsigned b[32][SBU_STR]; };  // 27136 B
struct SmemV { unsigned a[64][SA_STR];  unsigned b[32][SBV_STR]; };  // 26112 B
union __align__(16) SmemG { SmemU u; SmemV v; };

// ---------------- dominant kernel: dual GEMM (mode by blockIdx.z) ----------
// z=0:  T_u[r][n][h]  = sum_m support[r][n][m] * Y[r][m][h]   (CTA 128n x 64h)
// z=1:  Tvt[r][h][m]  = sum_n Xh[r][h][n] * support[r][n][m]  (CTA 64h x 128m)
__global__ __launch_bounds__(256,2) void k_gemm(const float* __restrict__ supp){
  __shared__ SmemG sm;
  const int r = blockIdx.y;
  const int tid = threadIdx.x;
  const int wid = tid>>5, lane = tid&31;
  const int l4 = lane>>2, lc = lane&3;
  float acc[2][4][4];
  #pragma unroll
  for(int i=0;i<2;i++)
    #pragma unroll
    for(int j=0;j<4;j++)
      #pragma unroll
      for(int k=0;k<4;k++) acc[i][j][k]=0.f;

  if(blockIdx.z == 0){
    const int n0 = blockIdx.x*128;
    const int wm = wid & 3, wn = wid >> 2;          // 4x2 warp grid (M x N)
    const float* A  = supp + ((size_t)r*NN + n0)*NN;
    const float* Bp = g_Y  + (size_t)r*NN*HH;
    for(int k0=0; k0<NN; k0+=32){
      #pragma unroll
      for(int i=0;i<4;i++){                         // A tile 128x32
        const int f = tid + i*256;
        const int row = f>>3, c4 = (f&7)*4;
        const float4 v = *reinterpret_cast<const float4*>(A + (size_t)row*NN + k0 + c4);
        *reinterpret_cast<uint4*>(&sm.u.a[row][c4]) =
          make_uint4(f2tf(v.x), f2tf(v.y), f2tf(v.z), f2tf(v.w));
      }
      #pragma unroll
      for(int i=0;i<2;i++){                         // B tile 32x64
        const int f = tid + i*256;
        const int row = f>>4, c4 = (f&15)*4;
        const float4 v = *reinterpret_cast<const float4*>(Bp + (size_t)(k0+row)*HH + c4);
        *reinterpret_cast<uint4*>(&sm.u.b[row][c4]) =
          make_uint4(f2tf(v.x), f2tf(v.y), f2tf(v.z), f2tf(v.w));
      }
      __syncthreads();
      #pragma unroll
      for(int ks=0; ks<4; ks++){
        const int k8 = ks*8;
        unsigned a[2][4];
        #pragma unroll
        for(int mi=0; mi<2; mi++){
          const int rr = wm*32 + mi*16 + l4;
          a[mi][0]=sm.u.a[rr  ][k8+lc];
          a[mi][1]=sm.u.a[rr+8][k8+lc];
          a[mi][2]=sm.u.a[rr  ][k8+lc+4];
          a[mi][3]=sm.u.a[rr+8][k8+lc+4];
        }
        #pragma unroll
        for(int ni=0; ni<4; ni++){
          unsigned b[2];
          const int cc = wn*32 + ni*8 + l4;
          b[0]=sm.u.b[k8+lc  ][cc];
          b[1]=sm.u.b[k8+lc+4][cc];
          mma8(acc[0][ni], a[0], b);
          mma8(acc[1][ni], a[1], b);
        }
      }
      __syncthreads();
    }
    float* Out = g_Tu + ((size_t)r*NN + n0)*HH;
    #pragma unroll
    for(int mi=0; mi<2; mi++){
      const int r0 = wm*32 + mi*16 + l4;
      #pragma unroll
      for(int ni=0; ni<4; ni++){
        const int h = wn*32 + ni*8 + lc*2;
        *reinterpret_cast<float2*>(&Out[(size_t)r0*HH + h])     = make_float2(acc[mi][ni][0], acc[mi][ni][1]);
        *reinterpret_cast<float2*>(&Out[(size_t)(r0+8)*HH + h]) = make_float2(acc[mi][ni][2], acc[mi][ni][3]);
      }
    }
  } else {
    const int m0 = blockIdx.x*128;
    const int wm = wid & 1, wn = wid >> 1;          // 2x4 warp grid (M x N)
    const float* A  = g_Xh + (size_t)r*HH*NN;       // [h][n]
    const float* Bp = supp + (size_t)r*NN*NN + m0;  // rows n, cols m
    for(int k0=0; k0<NN; k0+=32){
      #pragma unroll
      for(int i=0;i<2;i++){                         // A tile 64x32
        const int f = tid + i*256;
        const int row = f>>3, c4 = (f&7)*4;
        const float4 v = *reinterpret_cast<const float4*>(A + (size_t)row*NN + k0 + c4);
        *reinterpret_cast<uint4*>(&sm.v.a[row][c4]) =
          make_uint4(f2tf(v.x), f2tf(v.y), f2tf(v.z), f2tf(v.w));
      }
      #pragma unroll
      for(int i=0;i<4;i++){                         // B tile 32x128
        const int f = tid + i*256;
        const int row = f>>5, c4 = (f&31)*4;
        const float4 v = *reinterpret_cast<const float4*>(Bp + (size_t)(k0+row)*NN + c4);
        *reinterpret_cast<uint4*>(&sm.v.b[row][c4]) =
          make_uint4(f2tf(v.x), f2tf(v.y), f2tf(v.z), f2tf(v.w));
      }
      __syncthreads();
      #pragma unroll
      for(int ks=0; ks<4; ks++){
        const int k8 = ks*8;
        unsigned a[2][4];
        #pragma unroll
        for(int mi=0; mi<2; mi++){
          const int rr = wm*32 + mi*16 + l4;
          a[mi][0]=sm.v.a[rr  ][k8+lc];
          a[mi][1]=sm.v.a[rr+8][k8+lc];
          a[mi][2]=sm.v.a[rr  ][k8+lc+4];
          a[mi][3]=sm.v.a[rr+8][k8+lc+4];
        }
        #pragma unroll
        for(int ni=0; ni<4; ni++){
          unsigned b[2];
          const int cc = wn*32 + ni*8 + l4;
          b[0]=sm.v.b[k8+lc  ][cc];
          b[1]=sm.v.b[k8+lc+4][cc];
          mma8(acc[0][ni], a[0], b);
          mma8(acc[1][ni], a[1], b);
        }
      }
      __syncthreads();
    }
    float* Out = g_Tvt + (size_t)r*HH*NN + m0;
    #pragma unroll
    for(int mi=0; mi<2; mi++){
      const int hr = wm*32 + mi*16 + l4;
      #pragma unroll
      for(int ni=0; ni<4; ni++){
        const int mcol = wn*32 + ni*8 + lc*2;
        *reinterpret_cast<float2*>(&Out[(size_t)hr*NN + mcol])     = make_float2(acc[mi][ni][0], acc[mi][ni][1]);
        *reinterpret_cast<float2*>(&Out[(size_t)(hr+8)*NN + mcol]) = make_float2(acc[mi][ni][2], acc[mi][ni][3]);
      }
    }
  }
}

// ---------------- gather + bias + relu -------------------------------------
__global__ void k_out(const int* __restrict__ u, const int* __restrict__ v,
                      const float* __restrict__ bias, float* __restrict__ out){
  const int b = blockIdx.x;
  const int h = threadIdx.x;  // 64
  const int ub = u[b], vb = v[b];
  float su = bias[h], sv = bias[h];
  #pragma unroll
  for(int r=0;r<RR;r++){
    su += g_cinv[r*NN + ub] * g_Tu [((size_t)r*NN + ub)*HH + h];
    sv += g_rinv[r*NN + vb] * g_Tvt[((size_t)r*HH + h)*NN + vb];
  }
  out[(size_t)b*HH + h]        = fmaxf(su, 0.f);
  out[(size_t)(BB + b)*HH + h] = fmaxf(sv, 0.f);
}

// ---------------- launch ----------------------------------------------------
extern "C" void kernel_launch(void* const* d_in, const int* in_sizes, int n_in,
                              void* d_out, int out_size){
  (void)in_sizes; (void)n_in; (void)out_size;
  const float* u_feat = (const float*)d_in[0];
  const float* v_feat = (const float*)d_in[1];
  const int*   u      = (const int*)  d_in[2];
  const int*   v      = (const int*)  d_in[3];
  const float* supp   = (const float*)d_in[4];
  const float* u_w    = (const float*)d_in[5];
  const float* v_w    = (const float*)d_in[6];
  const float* u_bias = (const float*)d_in[7];
  float* out = (float*)d_out;

  k_sums   <<<dim3(32, 8, RR), 128>>>(supp);
  k_reduce <<<160, 256>>>();
  k_weights<<<64, 256>>>(u_w, v_w);
  k_tmp    <<<dim3(1024, RR, 2), 256>>>(u_feat, v_feat);
  k_gemm   <<<dim3(32, RR, 2), 256>>>(supp);
  k_out    <<<BB, HH>>>(u, v, u_bias, out);
}

// round 4
// speedup vs baseline: 1.6125x; 1.6125x over previous
#include <cuda_runtime.h>
#include <cstdint>

#define RR 5
#define NN 4096
#define DD 256
#define HH 64
#define BB 4096

// ---------------- scratch (static device globals; no allocs allowed) -------
__device__ float g_uw[RR*DD*HH];            // cumsum(u_weight)
__device__ float g_vw[RR*DD*HH];            // cumsum(v_weight)
__device__ float g_rowPart[RR*32*NN];       // partial row sums  [r][mchunk][n]
__device__ float g_colPart[RR*8*NN];        // partial col sums  [r][nchunk][m]
__device__ float g_cinv[RR*NN];             // rsqrt(row-sums)  (index n)
__device__ float g_rinv[RR*NN];             // rsqrt(col-sums)  (index m)
__device__ float g_Xh[(size_t)RR*HH*NN];    // X^T (tf32 bits)  [r][h][n]
__device__ float g_Y [(size_t)RR*NN*HH];    // Y   (tf32 bits)  [r][m][h]
__device__ float g_Tu[(size_t)RR*NN*HH];    // T_u  [r][n][h]
__device__ float g_Tvt[(size_t)RR*HH*NN];   // T_v^T [r][h][m]

// ---------------- pass 1: row/col sums of support (deterministic) ---------
__global__ void k_sums(const float* __restrict__ supp){
  const int r = blockIdx.z, mc = blockIdx.x, nc = blockIdx.y;
  const int m0 = mc*128, n0 = nc*512;
  const int w = threadIdx.x>>5, lane = threadIdx.x&31;
  const float* base = supp + (size_t)r*NN*NN + m0 + lane*4;
  float cx=0.f, cy=0.f, cz=0.f, cw=0.f;
  float* rp = g_rowPart + ((size_t)r*32 + mc)*NN;
  #pragma unroll 4
  for(int i=0;i<128;i++){
    const int n = n0 + w*128 + i;
    const float4 v = *reinterpret_cast<const float4*>(base + (size_t)n*NN);
    float s = v.x+v.y+v.z+v.w;
    cx+=v.x; cy+=v.y; cz+=v.z; cw+=v.w;
    #pragma unroll
    for(int o=16;o;o>>=1) s += __shfl_xor_sync(0xffffffffu, s, o);
    if(lane==0) rp[n] = s;
  }
  __shared__ float sc[4][128];
  sc[w][lane*4+0]=cx; sc[w][lane*4+1]=cy; sc[w][lane*4+2]=cz; sc[w][lane*4+3]=cw;
  __syncthreads();
  if(threadIdx.x < 128){
    float s = sc[0][threadIdx.x]+sc[1][threadIdx.x]+sc[2][threadIdx.x]+sc[3][threadIdx.x];
    g_colPart[((size_t)r*8 + nc)*NN + m0 + threadIdx.x] = s;
  }
}

// ---------------- pass 2: reduce partials -> c_inv / r_inv -----------------
__global__ void k_reduce(){
  const int idx = blockIdx.x*256 + threadIdx.x;   // grid 160 -> 40960 threads
  if(idx < RR*NN){
    const int r = idx/NN, n = idx%NN;
    float s=0.f;
    #pragma unroll
    for(int mc=0; mc<32; mc++) s += g_rowPart[((size_t)r*32+mc)*NN + n];
    g_cinv[idx] = (s>0.f)? rsqrtf(s) : 0.f;
  } else {
    const int j = idx - RR*NN;
    const int r = j/NN, m = j%NN;
    float s=0.f;
    #pragma unroll
    for(int nc=0; nc<8; nc++) s += g_colPart[((size_t)r*8+nc)*NN + m];
    g_rinv[j] = (s>0.f)? rsqrtf(s) : 0.f;
  }
}

// ---------------- weight cumsum over relations -----------------------------
__global__ void k_weights(const float* __restrict__ uw, const float* __restrict__ vw){
  const int i = blockIdx.x*256 + threadIdx.x;     // grid 64 -> 16384
  float au=0.f, av=0.f;
  #pragma unroll
  for(int r=0;r<RR;r++){
    au += uw[r*DD*HH + i]; g_uw[r*DD*HH + i] = au;
    av += vw[r*DD*HH + i]; g_vw[r*DD*HH + i] = av;
  }
}

// ---------------- TF32 / mma helpers ---------------------------------------
__device__ __forceinline__ unsigned f2tf(float x){
  unsigned r; asm("cvt.rna.tf32.f32 %0, %1;" : "=r"(r) : "f"(x)); return r;
}
__device__ __forceinline__ void mma8(float* c, const unsigned* a, const unsigned* b){
  asm volatile("mma.sync.aligned.m16n8k8.row.col.f32.tf32.tf32.f32 "
    "{%0,%1,%2,%3},{%4,%5,%6,%7},{%8,%9},{%0,%1,%2,%3};"
    : "+f"(c[0]),"+f"(c[1]),"+f"(c[2]),"+f"(c[3])
    : "r"(a[0]),"r"(a[1]),"r"(a[2]),"r"(a[3]),"r"(b[0]),"r"(b[1]));
}
__device__ __forceinline__ void cpa16(uint32_t dst, const void* src){
  asm volatile("cp.async.cg.shared.global [%0], [%1], 16;" :: "r"(dst), "l"(src));
}
#define CP_COMMIT asm volatile("cp.async.commit_group;" ::: "memory")
#define CP_WAIT1  asm volatile("cp.async.wait_group 1;"  ::: "memory")

// smem tiles, K-chunk = 16.
// A stride 20 words: banks (20*l4 + lc) mod 32 all distinct -> conflict-free.
// B stride 72/136 words (== 8 mod 32): banks lc*8 + l4 all distinct -> conflict-free.
#define A_STR 20
#define BU_STR 72
#define BV_STR 136
#define STG_U ((128*A_STR + 16*BU_STR)*4)   // 14848 B
#define STG_V ((64*A_STR + 16*BV_STR)*4)    // 13824 B

// Warp-tile compute on a K=16 stage: 2x m16n8k8 K-steps, 32x32 per warp pair-grid.
template<int BS>
__device__ __forceinline__ void tile_mma(const unsigned* __restrict__ Ab,
                                         const unsigned* __restrict__ Bb,
                                         int wm,int wn,int l4,int lc,
                                         float acc[2][4][4]){
  #pragma unroll
  for(int ks=0; ks<2; ks++){
    const int k8 = ks*8;
    unsigned a[2][4];
    #pragma unroll
    for(int mi=0; mi<2; mi++){
      const int rr = wm*32 + mi*16 + l4;
      a[mi][0]=Ab[rr*A_STR     + k8+lc];
      a[mi][1]=Ab[(rr+8)*A_STR + k8+lc];
      a[mi][2]=Ab[rr*A_STR     + k8+lc+4];
      a[mi][3]=Ab[(rr+8)*A_STR + k8+lc+4];
    }
    #pragma unroll
    for(int ni=0; ni<4; ni++){
      unsigned b[2];
      const int cc = wn*32 + ni*8 + l4;
      b[0]=Bb[(k8+lc)*BS   + cc];
      b[1]=Bb[(k8+lc+4)*BS + cc];
      mma8(acc[0][ni], a[0], b);
      mma8(acc[1][ni], a[1], b);
    }
  }
}

// ---------------- k_tmp2: tmp_u/tmp_v via mma, scaled, stored as tf32 ------
// side 0: Xh[r][h][n] = RNA_tf32( (u_feat @ cum_uw)[n][h] * cinv[r][n] )
// side 1: Y [r][n][h] = RNA_tf32( (v_feat @ cum_vw)[n][h] * rinv[r][n] )
__global__ __launch_bounds__(256) void k_tmp2(const float* __restrict__ uf,
                                              const float* __restrict__ vf){
  __shared__ __align__(16) unsigned char smbuf[STG_U];
  const int side = blockIdx.z, r = blockIdx.y, n0 = blockIdx.x*128;
  const int tid = threadIdx.x;
  const int wid = tid>>5, lane = tid&31, l4 = lane>>2, lc = lane&3;
  const int wm = wid&3, wn = wid>>2;
  const float* feat = (side ? vf : uf) + (size_t)n0*DD;
  const float* wgt  = (side ? g_vw : g_uw) + r*DD*HH;
  unsigned* Ab = (unsigned*)smbuf;
  unsigned* Bb = Ab + 128*A_STR;
  float acc[2][4][4];
  #pragma unroll
  for(int i=0;i<2;i++) for(int j=0;j<4;j++) for(int k=0;k<4;k++) acc[i][j][k]=0.f;

  for(int k0=0; k0<DD; k0+=16){
    #pragma unroll
    for(int i=0;i<2;i++){
      const int f = tid + i*256, row = f>>2, c = (f&3)*4;
      const float4 v = *reinterpret_cast<const float4*>(feat + (size_t)row*DD + k0 + c);
      *reinterpret_cast<uint4*>(Ab + row*A_STR + c) =
        make_uint4(f2tf(v.x), f2tf(v.y), f2tf(v.z), f2tf(v.w));
    }
    {
      const int row = tid>>4, c = (tid&15)*4;
      const float4 v = *reinterpret_cast<const float4*>(wgt + (size_t)(k0+row)*HH + c);
      *reinterpret_cast<uint4*>(Bb + row*BU_STR + c) =
        make_uint4(f2tf(v.x), f2tf(v.y), f2tf(v.z), f2tf(v.w));
    }
    __syncthreads();
    tile_mma<BU_STR>(Ab, Bb, wm, wn, l4, lc, acc);
    __syncthreads();
  }
  const float* sv = (side ? g_rinv : g_cinv) + r*NN;
  #pragma unroll
  for(int mi=0; mi<2; mi++){
    const int n = n0 + wm*32 + mi*16 + l4;
    const float s0 = sv[n], s1 = sv[n+8];
    #pragma unroll
    for(int ni=0; ni<4; ni++){
      const int h = wn*32 + ni*8 + lc*2;
      if(side==0){
        g_Xh[((size_t)r*HH + h  )*NN + n  ] = __uint_as_float(f2tf(acc[mi][ni][0]*s0));
        g_Xh[((size_t)r*HH + h+1)*NN + n  ] = __uint_as_float(f2tf(acc[mi][ni][1]*s0));
        g_Xh[((size_t)r*HH + h  )*NN + n+8] = __uint_as_float(f2tf(acc[mi][ni][2]*s1));
        g_Xh[((size_t)r*HH + h+1)*NN + n+8] = __uint_as_float(f2tf(acc[mi][ni][3]*s1));
      } else {
        g_Y[((size_t)r*NN + n  )*HH + h  ] = __uint_as_float(f2tf(acc[mi][ni][0]*s0));
        g_Y[((size_t)r*NN + n  )*HH + h+1] = __uint_as_float(f2tf(acc[mi][ni][1]*s0));
        g_Y[((size_t)r*NN + n+8)*HH + h  ] = __uint_as_float(f2tf(acc[mi][ni][2]*s1));
        g_Y[((size_t)r*NN + n+8)*HH + h+1] = __uint_as_float(f2tf(acc[mi][ni][3]*s1));
      }
    }
  }
}

// ---------------- dominant kernel: dual GEMM, cp.async 3-stage pipeline ----
// z=0:  T_u[r][n][h]  = sum_m support[r][n][m] * Y[r][m][h]   (CTA 128n x 64h)
// z=1:  Tvt[r][h][m]  = sum_n Xh[r][h][n] * support[r][n][m]  (CTA 64h x 128m)
// support fed raw (HW tf32 truncation); Y/Xh are pre-rounded tf32 bits.
__global__ __launch_bounds__(256,2) void k_gemm(const float* __restrict__ supp){
  __shared__ __align__(16) unsigned char smbuf[3*STG_U];   // 44544 B (>= 3*STG_V)
  const int r = blockIdx.y;
  const int tid = threadIdx.x;
  const int wid = tid>>5, lane = tid&31, l4 = lane>>2, lc = lane&3;
  const uint32_t smb = (uint32_t)__cvta_generic_to_shared(smbuf);
  float acc[2][4][4];
  #pragma unroll
  for(int i=0;i<2;i++) for(int j=0;j<4;j++) for(int k=0;k<4;k++) acc[i][j][k]=0.f;

  if(blockIdx.z == 0){
    const int n0 = blockIdx.x*128;
    const int wm = wid & 3, wn = wid >> 2;          // 4x2 warp grid
    const float* A  = supp + ((size_t)r*NN + n0)*NN;
    const float* Bp = g_Y  + (size_t)r*NN*HH;
    auto load = [&](int s, int k0){
      const uint32_t sa = smb + (uint32_t)s*STG_U;
      const uint32_t sb = sa + 128*A_STR*4;
      #pragma unroll
      for(int i=0;i<2;i++){
        const int f = tid + i*256, row = f>>2, c = (f&3)*4;
        cpa16(sa + (uint32_t)(row*A_STR + c)*4u, A + (size_t)row*NN + k0 + c);
      }
      const int row = tid>>4, c = (tid&15)*4;
      cpa16(sb + (uint32_t)(row*BU_STR + c)*4u, Bp + (size_t)(k0+row)*HH + c);
    };
    load(0,0); CP_COMMIT; load(1,16); CP_COMMIT;
    for(int it=0; it<NN/16; it++){
      CP_WAIT1; __syncthreads();
      const unsigned* Ab = (const unsigned*)(smbuf + (it%3)*STG_U);
      tile_mma<BU_STR>(Ab, Ab + 128*A_STR, wm, wn, l4, lc, acc);
      if(it+2 < NN/16) load((it+2)%3, (it+2)*16);
      CP_COMMIT;
    }
    float* Out = g_Tu + ((size_t)r*NN + n0)*HH;
    #pragma unroll
    for(int mi=0; mi<2; mi++){
      const int r0 = wm*32 + mi*16 + l4;
      #pragma unroll
      for(int ni=0; ni<4; ni++){
        const int h = wn*32 + ni*8 + lc*2;
        *reinterpret_cast<float2*>(&Out[(size_t)r0*HH + h])     = make_float2(acc[mi][ni][0], acc[mi][ni][1]);
        *reinterpret_cast<float2*>(&Out[(size_t)(r0+8)*HH + h]) = make_float2(acc[mi][ni][2], acc[mi][ni][3]);
      }
    }
  } else {
    const int m0 = blockIdx.x*128;
    const int wm = wid & 1, wn = wid >> 1;          // 2x4 warp grid
    const float* A  = g_Xh + (size_t)r*HH*NN;       // [h][n], tf32 bits
    const float* Bp = supp + (size_t)r*NN*NN + m0;  // rows n, cols m
    auto load = [&](int s, int k0){
      const uint32_t sa = smb + (uint32_t)s*STG_V;
      const uint32_t sb = sa + 64*A_STR*4;
      {
        const int row = tid>>2, c = (tid&3)*4;
        cpa16(sa + (uint32_t)(row*A_STR + c)*4u, A + (size_t)row*NN + k0 + c);
      }
      #pragma unroll
      for(int i=0;i<2;i++){
        const int f = tid + i*256, row = f>>5, c = (f&31)*4;
        cpa16(sb + (uint32_t)(row*BV_STR + c)*4u, Bp + (size_t)(k0+row)*NN + c);
      }
    };
    load(0,0); CP_COMMIT; load(1,16); CP_COMMIT;
    for(int it=0; it<NN/16; it++){
      CP_WAIT1; __syncthreads();
      const unsigned* Ab = (const unsigned*)(smbuf + (it%3)*STG_V);
      tile_mma<BV_STR>(Ab, Ab + 64*A_STR, wm, wn, l4, lc, acc);
      if(it+2 < NN/16) load((it+2)%3, (it+2)*16);
      CP_COMMIT;
    }
    float* Out = g_Tvt + (size_t)r*HH*NN + m0;
    #pragma unroll
    for(int mi=0; mi<2; mi++){
      const int hr = wm*32 + mi*16 + l4;
      #pragma unroll
      for(int ni=0; ni<4; ni++){
        const int mcol = wn*32 + ni*8 + lc*2;
        *reinterpret_cast<float2*>(&Out[(size_t)hr*NN + mcol])     = make_float2(acc[mi][ni][0], acc[mi][ni][1]);
        *reinterpret_cast<float2*>(&Out[(size_t)(hr+8)*NN + mcol]) = make_float2(acc[mi][ni][2], acc[mi][ni][3]);
      }
    }
  }
}

// ---------------- gather + bias + relu -------------------------------------
__global__ void k_out(const int* __restrict__ u, const int* __restrict__ v,
                      const float* __restrict__ bias, float* __restrict__ out){
  const int b = blockIdx.x;
  const int h = threadIdx.x;  // 64
  const int ub = u[b], vb = v[b];
  float su = bias[h], sv = bias[h];
  #pragma unroll
  for(int r=0;r<RR;r++){
    su += g_cinv[r*NN + ub] * g_Tu [((size_t)r*NN + ub)*HH + h];
    sv += g_rinv[r*NN + vb] * g_Tvt[((size_t)r*HH + h)*NN + vb];
  }
  out[(size_t)b*HH + h]        = fmaxf(su, 0.f);
  out[(size_t)(BB + b)*HH + h] = fmaxf(sv, 0.f);
}

// ---------------- launch ----------------------------------------------------
extern "C" void kernel_launch(void* const* d_in, const int* in_sizes, int n_in,
                              void* d_out, int out_size){
  (void)in_sizes; (void)n_in; (void)out_size;
  const float* u_feat = (const float*)d_in[0];
  const float* v_feat = (const float*)d_in[1];
  const int*   u      = (const int*)  d_in[2];
  const int*   v      = (const int*)  d_in[3];
  const float* supp   = (const float*)d_in[4];
  const float* u_w    = (const float*)d_in[5];
  const float* v_w    = (const float*)d_in[6];
  const float* u_bias = (const float*)d_in[7];
  float* out = (float*)d_out;

  k_sums   <<<dim3(32, 8, RR), 128>>>(supp);
  k_reduce <<<160, 256>>>();
  k_weights<<<64, 256>>>(u_w, v_w);
  k_tmp2   <<<dim3(32, RR, 2), 256>>>(u_feat, v_feat);
  k_gemm   <<<dim3(32, RR, 2), 256>>>(supp);
  k_out    <<<BB, HH>>>(u, v, u_bias, out);
}

// round 6
// speedup vs baseline: 1.8889x; 1.1714x over previous
#include <cuda_runtime.h>
#include <cstdint>

#define RR 5
#define NN 4096
#define DD 256
#define HH 64
#define BB 4096

// ---------------- scratch (static device globals; no allocs allowed) -------
__device__ float g_uw[RR*DD*HH];            // cumsum(u_weight)
__device__ float g_vw[RR*DD*HH];            // cumsum(v_weight)
__device__ float g_rowPart[RR*32*NN];
__device__ float g_colPart[RR*8*NN];
__device__ float g_cinv[RR*NN];             // index n
__device__ float g_rinv[RR*NN];             // index m
__device__ float g_Xh[(size_t)RR*HH*NN];    // X^T (tf32-rounded) [r][h][n]
__device__ float g_Y [(size_t)RR*NN*HH];    // Y   (tf32-rounded) [r][m][h]
__device__ float g_Tu[(size_t)RR*NN*HH];    // [r][n][h]
__device__ float g_Tvt[(size_t)RR*HH*NN];   // [r][h][m]

// ---------------- pass 1: row/col sums of support --------------------------
__global__ void k_sums(const float* __restrict__ supp){
  const int r = blockIdx.z, mc = blockIdx.x, nc = blockIdx.y;
  const int m0 = mc*128, n0 = nc*512;
  const int w = threadIdx.x>>5, lane = threadIdx.x&31;
  const float* base = supp + (size_t)r*NN*NN + m0 + lane*4;
  float cx=0.f, cy=0.f, cz=0.f, cw=0.f;
  float* rp = g_rowPart + ((size_t)r*32 + mc)*NN;
  #pragma unroll 4
  for(int i=0;i<128;i++){
    const int n = n0 + w*128 + i;
    const float4 v = *reinterpret_cast<const float4*>(base + (size_t)n*NN);
    float s = v.x+v.y+v.z+v.w;
    cx+=v.x; cy+=v.y; cz+=v.z; cw+=v.w;
    #pragma unroll
    for(int o=16;o;o>>=1) s += __shfl_xor_sync(0xffffffffu, s, o);
    if(lane==0) rp[n] = s;
  }
  __shared__ float sc[4][128];
  sc[w][lane*4+0]=cx; sc[w][lane*4+1]=cy; sc[w][lane*4+2]=cz; sc[w][lane*4+3]=cw;
  __syncthreads();
  if(threadIdx.x < 128){
    float s = sc[0][threadIdx.x]+sc[1][threadIdx.x]+sc[2][threadIdx.x]+sc[3][threadIdx.x];
    g_colPart[((size_t)r*8 + nc)*NN + m0 + threadIdx.x] = s;
  }
}

__global__ void k_reduce(){
  const int idx = blockIdx.x*256 + threadIdx.x;
  if(idx < RR*NN){
    const int r = idx/NN, n = idx%NN;
    float s=0.f;
    #pragma unroll
    for(int mc=0; mc<32; mc++) s += g_rowPart[((size_t)r*32+mc)*NN + n];
    g_cinv[idx] = (s>0.f)? rsqrtf(s) : 0.f;
  } else {
    const int j = idx - RR*NN;
    const int r = j/NN, m = j%NN;
    float s=0.f;
    #pragma unroll
    for(int nc=0; nc<8; nc++) s += g_colPart[((size_t)r*8+nc)*NN + m];
    g_rinv[j] = (s>0.f)? rsqrtf(s) : 0.f;
  }
}

__global__ void k_weights(const float* __restrict__ uw, const float* __restrict__ vw){
  const int i = blockIdx.x*256 + threadIdx.x;
  float au=0.f, av=0.f;
  #pragma unroll
  for(int r=0;r<RR;r++){
    au += uw[r*DD*HH + i]; g_uw[r*DD*HH + i] = au;
    av += vw[r*DD*HH + i]; g_vw[r*DD*HH + i] = av;
  }
}

// ---------------- TF32 / mma helpers ---------------------------------------
__device__ __forceinline__ unsigned f2tf(float x){
  unsigned r; asm("cvt.rna.tf32.f32 %0, %1;" : "=r"(r) : "f"(x)); return r;
}
__device__ __forceinline__ void mma8(float* c, const unsigned* a, const unsigned* b){
  asm volatile("mma.sync.aligned.m16n8k8.row.col.f32.tf32.tf32.f32 "
    "{%0,%1,%2,%3},{%4,%5,%6,%7},{%8,%9},{%0,%1,%2,%3};"
    : "+f"(c[0]),"+f"(c[1]),"+f"(c[2]),"+f"(c[3])
    : "r"(a[0]),"r"(a[1]),"r"(a[2]),"r"(a[3]),"r"(b[0]),"r"(b[1]));
}
__device__ __forceinline__ void cpa16(uint32_t dst, const void* src){
  asm volatile("cp.async.cg.shared.global [%0], [%1], 16;" :: "r"(dst), "l"(src));
}
#define CP_COMMIT asm volatile("cp.async.commit_group;" ::: "memory")
#define CP_WAIT1  asm volatile("cp.async.wait_group 1;"  ::: "memory")

// K-chunk 32 smem layout (word strides):
// A: 128(or 64) rows x 32 words, stride 36 -> frag banks (4*l4+lc) distinct.
// B: 32 k-rows x 64/128 words, stride 72/136 (==8 mod 32) -> banks (8*lc+l4) distinct.
#define A_STR 36
#define BU_STR 72
#define BV_STR 136
#define STG_WORDS (128*A_STR + 32*BU_STR)   // 6912 words = 27648 B (z1 needs 6656)
#define STG_BYTES (STG_WORDS*4)
#define DYN_BYTES (3*STG_BYTES)             // 82944 B, occupancy 2

// frag load for one k8 step
template<int BS>
__device__ __forceinline__ void load_frag(const unsigned* __restrict__ Ab,
                                          const unsigned* __restrict__ Bb,
                                          int wm,int wn,int l4,int lc,int k8,
                                          unsigned a[2][4], unsigned b[4][2]){
  #pragma unroll
  for(int mi=0; mi<2; mi++){
    const int rr = wm*32 + mi*16 + l4;
    a[mi][0]=Ab[rr*A_STR     + k8+lc];
    a[mi][1]=Ab[(rr+8)*A_STR + k8+lc];
    a[mi][2]=Ab[rr*A_STR     + k8+lc+4];
    a[mi][3]=Ab[(rr+8)*A_STR + k8+lc+4];
  }
  #pragma unroll
  for(int ni=0; ni<4; ni++){
    const int cc = wn*32 + ni*8 + l4;
    b[ni][0]=Bb[(k8+lc)*BS   + cc];
    b[ni][1]=Bb[(k8+lc+4)*BS + cc];
  }
}

// one K=32 chunk: 4 k8 steps, register double-buffered
template<int BS>
__device__ __forceinline__ void chunk_mma(const unsigned* __restrict__ Ab,
                                          const unsigned* __restrict__ Bb,
                                          int wm,int wn,int l4,int lc,
                                          float acc[2][4][4]){
  unsigned a[2][2][4], b[2][4][2];
  load_frag<BS>(Ab,Bb,wm,wn,l4,lc,0,a[0],b[0]);
  #pragma unroll
  for(int ks=0; ks<4; ks++){
    const int cur = ks&1;
    if(ks<3) load_frag<BS>(Ab,Bb,wm,wn,l4,lc,(ks+1)*8,a[cur^1],b[cur^1]);
    #pragma unroll
    for(int ni=0; ni<4; ni++){
      mma8(acc[0][ni], a[cur][0], b[cur][ni]);
      mma8(acc[1][ni], a[cur][1], b[cur][ni]);
    }
  }
}

// ---------------- k_tmp2: Xh / Y via mma (raw fp32 operands) ---------------
// side 0: Xh[r][h][n] = tf32( (u_feat @ cum_uw)[n][h] * cinv[r][n] )
// side 1: Y [r][m][h] = tf32( (v_feat @ cum_vw)[m][h] * rinv[r][m] )
#define TA_STR 20
__global__ __launch_bounds__(128) void k_tmp2(const float* __restrict__ uf,
                                              const float* __restrict__ vf){
  __shared__ __align__(16) unsigned smA[64*TA_STR];
  __shared__ __align__(16) unsigned smB[16*BU_STR];
  const int side = blockIdx.z, r = blockIdx.y, n0 = blockIdx.x*64;
  const int tid = threadIdx.x;
  const int wid = tid>>5, lane = tid&31, l4 = lane>>2, lc = lane&3;
  const int wm = wid&1, wn = wid>>1;
  const float* feat = (side ? vf : uf) + (size_t)n0*DD;
  const float* wgt  = (side ? g_vw : g_uw) + r*DD*HH;
  float acc[2][4][4];
  #pragma unroll
  for(int i=0;i<2;i++) for(int j=0;j<4;j++) for(int k=0;k<4;k++) acc[i][j][k]=0.f;

  for(int k0=0; k0<DD; k0+=16){
    #pragma unroll
    for(int i=0;i<2;i++){                      // A 64x16 raw
      const int f = tid + i*128, row = f>>2, c = (f&3)*4;
      *reinterpret_cast<uint4*>(smA + row*TA_STR + c) =
        *reinterpret_cast<const uint4*>(feat + (size_t)row*DD + k0 + c);
    }
    #pragma unroll
    for(int i=0;i<2;i++){                      // B 16x64 raw
      const int f = tid + i*128, row = f>>4, c = (f&15)*4;
      *reinterpret_cast<uint4*>(smB + row*BU_STR + c) =
        *reinterpret_cast<const uint4*>(wgt + (size_t)(k0+row)*HH + c);
    }
    __syncthreads();
    #pragma unroll
    for(int ks=0; ks<2; ks++){
      const int k8 = ks*8;
      unsigned a[2][4];
      #pragma unroll
      for(int mi=0; mi<2; mi++){
        const int rr = wm*32 + mi*16 + l4;
        a[mi][0]=smA[rr*TA_STR     + k8+lc];
        a[mi][1]=smA[(rr+8)*TA_STR + k8+lc];
        a[mi][2]=smA[rr*TA_STR     + k8+lc+4];
        a[mi][3]=smA[(rr+8)*TA_STR + k8+lc+4];
      }
      #pragma unroll
      for(int ni=0; ni<4; ni++){
        unsigned b[2];
        const int cc = wn*32 + ni*8 + l4;
        b[0]=smB[(k8+lc)*BU_STR   + cc];
        b[1]=smB[(k8+lc+4)*BU_STR + cc];
        mma8(acc[0][ni], a[0], b);
        mma8(acc[1][ni], a[1], b);
      }
    }
    __syncthreads();
  }
  const float* sv = (side ? g_rinv : g_cinv) + r*NN;
  #pragma unroll
  for(int mi=0; mi<2; mi++){
    const int n = n0 + wm*32 + mi*16 + l4;
    const float s0 = sv[n], s1 = sv[n+8];
    #pragma unroll
    for(int ni=0; ni<4; ni++){
      const int h = wn*32 + ni*8 + lc*2;
      if(side==0){
        g_Xh[((size_t)r*HH + h  )*NN + n  ] = __uint_as_float(f2tf(acc[mi][ni][0]*s0));
        g_Xh[((size_t)r*HH + h+1)*NN + n  ] = __uint_as_float(f2tf(acc[mi][ni][1]*s0));
        g_Xh[((size_t)r*HH + h  )*NN + n+8] = __uint_as_float(f2tf(acc[mi][ni][2]*s1));
        g_Xh[((size_t)r*HH + h+1)*NN + n+8] = __uint_as_float(f2tf(acc[mi][ni][3]*s1));
      } else {
        g_Y[((size_t)r*NN + n  )*HH + h  ] = __uint_as_float(f2tf(acc[mi][ni][0]*s0));
        g_Y[((size_t)r*NN + n  )*HH + h+1] = __uint_as_float(f2tf(acc[mi][ni][1]*s0));
        g_Y[((size_t)r*NN + n+8)*HH + h  ] = __uint_as_float(f2tf(acc[mi][ni][2]*s1));
        g_Y[((size_t)r*NN + n+8)*HH + h+1] = __uint_as_float(f2tf(acc[mi][ni][3]*s1));
      }
    }
  }
}

// ---------------- dominant kernel: dual GEMM, K32 chunks, 3-stage cp.async -
// z=0:  T_u[r][n][h]  = sum_m supp[r][n][m] * Y[r][m][h]   (CTA 128n x 64h)
// z=1:  Tvt[r][h][m]  = sum_n Xh[r][h][n] * supp[r][n][m]  (CTA 64h x 128m)
// support fed raw (HW tf32 truncation); Y/Xh pre-rounded tf32.
__global__ __launch_bounds__(256,2) void k_gemm(const float* __restrict__ supp){
  extern __shared__ __align__(16) unsigned char smbuf[];
  const int r = blockIdx.y;
  const int tid = threadIdx.x;
  const int wid = tid>>5, lane = tid&31, l4 = lane>>2, lc = lane&3;
  const uint32_t smb = (uint32_t)__cvta_generic_to_shared(smbuf);
  float acc[2][4][4];
  #pragma unroll
  for(int i=0;i<2;i++) for(int j=0;j<4;j++) for(int k=0;k<4;k++) acc[i][j][k]=0.f;

  if(blockIdx.z == 0){
    const int n0 = blockIdx.x*128;
    const int wm = wid & 3, wn = wid >> 2;          // 4x2 warp grid
    const float* A  = supp + ((size_t)r*NN + n0)*NN;
    const float* Bp = g_Y  + (size_t)r*NN*HH;
    auto load = [&](int j){
      const uint32_t sa = smb + (uint32_t)(j%3)*STG_BYTES;
      const uint32_t sb = sa + 128*A_STR*4;
      const int k0 = j*32;
      #pragma unroll
      for(int i=0;i<4;i++){                         // A 128x32
        const int f = tid + i*256, row = f>>3, c = (f&7)*4;
        cpa16(sa + (uint32_t)(row*A_STR + c)*4u, A + (size_t)row*NN + k0 + c);
      }
      #pragma unroll
      for(int i=0;i<2;i++){                         // B 32x64
        const int f = tid + i*256, row = f>>4, c = (f&15)*4;
        cpa16(sb + (uint32_t)(row*BU_STR + c)*4u, Bp + (size_t)(k0+row)*HH + c);
      }
    };
    load(0); CP_COMMIT; load(1); CP_COMMIT;
    for(int it=0; it<NN/32; it++){
      CP_WAIT1; __syncthreads();
      const unsigned* Ab = (const unsigned*)(smbuf + (it%3)*STG_BYTES);
      chunk_mma<BU_STR>(Ab, Ab + 128*A_STR, wm, wn, l4, lc, acc);
      if(it+2 < NN/32) load(it+2);
      CP_COMMIT;
    }
    float* Out = g_Tu + ((size_t)r*NN + n0)*HH;
    #pragma unroll
    for(int mi=0; mi<2; mi++){
      const int r0 = wm*32 + mi*16 + l4;
      #pragma unroll
      for(int ni=0; ni<4; ni++){
        const int h = wn*32 + ni*8 + lc*2;
        *reinterpret_cast<float2*>(&Out[(size_t)r0*HH + h])     = make_float2(acc[mi][ni][0], acc[mi][ni][1]);
        *reinterpret_cast<float2*>(&Out[(size_t)(r0+8)*HH + h]) = make_float2(acc[mi][ni][2], acc[mi][ni][3]);
      }
    }
  } else {
    const int m0 = blockIdx.x*128;
    const int wm = wid & 1, wn = wid >> 1;          // 2x4 warp grid
    const float* A  = g_Xh + (size_t)r*HH*NN;       // [h][n]
    const float* Bp = supp + (size_t)r*NN*NN + m0;  // rows n(K), cols m
    auto load = [&](int j){
      const uint32_t sa = smb + (uint32_t)(j%3)*STG_BYTES;
      const uint32_t sb = sa + 64*A_STR*4;
      const int k0 = j*32;
      #pragma unroll
      for(int i=0;i<2;i++){                         // A 64x32
        const int f = tid + i*256, row = f>>3, c = (f&7)*4;
        cpa16(sa + (uint32_t)(row*A_STR + c)*4u, A + (size_t)row*NN + k0 + c);
      }
      #pragma unroll
      for(int i=0;i<4;i++){                         // B 32x128
        const int f = tid + i*256, row = f>>5, c = (f&31)*4;
        cpa16(sb + (uint32_t)(row*BV_STR + c)*4u, Bp + (size_t)(k0+row)*NN + c);
      }
    };
    load(0); CP_COMMIT; load(1); CP_COMMIT;
    for(int it=0; it<NN/32; it++){
      CP_WAIT1; __syncthreads();
      const unsigned* Ab = (const unsigned*)(smbuf + (it%3)*STG_BYTES);
      chunk_mma<BV_STR>(Ab, Ab + 64*A_STR, wm, wn, l4, lc, acc);
      if(it+2 < NN/32) load(it+2);
      CP_COMMIT;
    }
    float* Out = g_Tvt + (size_t)r*HH*NN + m0;
    #pragma unroll
    for(int mi=0; mi<2; mi++){
      const int hr = wm*32 + mi*16 + l4;
      #pragma unroll
      for(int ni=0; ni<4; ni++){
        const int mcol = wn*32 + ni*8 + lc*2;
        *reinterpret_cast<float2*>(&Out[(size_t)hr*NN + mcol])     = make_float2(acc[mi][ni][0], acc[mi][ni][1]);
        *reinterpret_cast<float2*>(&Out[(size_t)(hr+8)*NN + mcol]) = make_float2(acc[mi][ni][2], acc[mi][ni][3]);
      }
    }
  }
}

// ---------------- gather + bias + relu -------------------------------------
__global__ void k_out(const int* __restrict__ u, const int* __restrict__ v,
                      const float* __restrict__ bias, float* __restrict__ out){
  const int b = blockIdx.x;
  const int h = threadIdx.x;  // 64
  const int ub = u[b], vb = v[b];
  float su = bias[h], sv = bias[h];
  #pragma unroll
  for(int r=0;r<RR;r++){
    su += g_cinv[r*NN + ub] * g_Tu [((size_t)r*NN + ub)*HH + h];
    sv += g_rinv[r*NN + vb] * g_Tvt[((size_t)r*HH + h)*NN + vb];
  }
  out[(size_t)b*HH + h]        = fmaxf(su, 0.f);
  out[(size_t)(BB + b)*HH + h] = fmaxf(sv, 0.f);
}

// ---------------- launch ----------------------------------------------------
extern "C" void kernel_launch(void* const* d_in, const int* in_sizes, int n_in,
                              void* d_out, int out_size){
  (void)in_sizes; (void)n_in; (void)out_size;
  const float* u_feat = (const float*)d_in[0];
  const float* v_feat = (const float*)d_in[1];
  const int*   u      = (const int*)  d_in[2];
  const int*   v      = (const int*)  d_in[3];
  const float* supp   = (const float*)d_in[4];
  const float* u_w    = (const float*)d_in[5];
  const float* v_w    = (const float*)d_in[6];
  const float* u_bias = (const float*)d_in[7];
  float* out = (float*)d_out;

  static int attr_done = 0;
  if(!attr_done){
    cudaFuncSetAttribute(k_gemm, cudaFuncAttributeMaxDynamicSharedMemorySize, DYN_BYTES);
    attr_done = 1;
  }

  k_sums   <<<dim3(32, 8, RR), 128>>>(supp);
  k_reduce <<<160, 256>>>();
  k_weights<<<64, 256>>>(u_w, v_w);
  k_tmp2   <<<dim3(64, RR, 2), 128>>>(u_feat, v_feat);
  k_gemm   <<<dim3(32, RR, 2), 256, DYN_BYTES>>>(supp);
  k_out    <<<BB, HH>>>(u, v, u_bias, out);
}